// round 3
// baseline (speedup 1.0000x reference)
#include <cuda_runtime.h>

// Diverse beam search step.
// Inputs (metadata order):
//  0 logprobs            f32 [B,K,V]
//  1 beam_seq            i32 [B,T,K]
//  2 beam_seq_logprobs   f32 [B,T,K]
//  3 beam_logprobs_sum   f32 [B,K]
//  4 state               f32 [2,2,B,K,H]
//  5 prev_decisions      i32 [B,16,K]
//  6 t                   int scalar (read low 32 bits)
// Output: f32 concat of (new_beam_seq, new_beam_seq_logprobs, sel_p, new_state)

#define Bn 128
#define Kn 16
#define Vn 50257
#define Tn 20
#define Hn 512
#define NPREV 256                  // 16*K tokens per batch
#define WPB ((Vn + 1) / 2)         // 25129 packed-uint16 words per batch
#define NBMW ((Vn + 31) / 32)      // 1571 bitmap words
#define NT 256
#define CH 2048

#define OFF_LPS   (Bn * Tn * Kn)                 // 40960
#define OFF_SELP  (2 * Bn * Tn * Kn)             // 81920
#define OFF_STATE (2 * Bn * Tn * Kn + Bn * Kn)   // 83968

__device__ unsigned g_cnt[Bn * WPB];                 // packed uint16 counts per (b, v)
__device__ unsigned long long g_cand[Bn * Kn * 16];  // per-beam top16 keys, rank-desc
__device__ int g_q[Bn * Kn];                         // selected source beam per (b, rank)

// ---------------- order-preserving float <-> uint32 ----------------
__device__ __forceinline__ unsigned ford(float x) {
    unsigned u = __float_as_uint(x);
    return u ^ (((unsigned)((int)u >> 31)) | 0x80000000u);
}
__device__ __forceinline__ float finv(unsigned o) {
    unsigned u = (o & 0x80000000u) ? (o ^ 0x80000000u) : ~o;
    return __uint_as_float(u);
}

// ---------------- counts: zero touched entries, then add ----------------
// The touched set is identical on every launch, so zeroing only those
// entries (instead of a 13MB memset) is graph-replay correct. Zeroing a
// packed word may clear a neighbor count, but that neighbor is then either
// untouched (stays 0, correct) or also re-added below.
__global__ void k_zero_counts(const int* __restrict__ prev) {
    int b = blockIdx.x, j = threadIdx.x;
    int tok = prev[b * NPREV + j];
    g_cnt[b * WPB + (tok >> 1)] = 0u;
}
__global__ void k_add_counts(const int* __restrict__ prev) {
    int b = blockIdx.x, j = threadIdx.x;
    int tok = prev[b * NPREV + j];
    atomicAdd(&g_cnt[b * WPB + (tok >> 1)], 1u << ((tok & 1) * 16));
}

// ---------------- per-beam streaming top-16 over V ----------------
// key = (ord(aug) << 32) | (0xFFFFFFFF - v): unique keys, larger key wins,
// ties on value resolve to smaller index == jax.lax.top_k semantics.
__global__ __launch_bounds__(NT) void k_beam_topk(const float* __restrict__ lp,
                                                  const int* __restrict__ prev) {
    __shared__ unsigned bm[NBMW];
    __shared__ unsigned long long buf[CH];
    __shared__ unsigned long long stop[16];
    __shared__ unsigned long long thr_s;
    __shared__ int nbuf_s;

    const int tid = threadIdx.x;
    const int bk = blockIdx.x;
    const int b = bk >> 4;
    const float* row = lp + (long)bk * Vn;
    const unsigned* cnt_row = g_cnt + (long)b * WPB;

    for (int i = tid; i < NBMW; i += NT) bm[i] = 0u;
    if (tid == 0) { nbuf_s = 0; thr_s = 0ull; }
    __syncthreads();
    {
        int tok = prev[b * NPREV + tid];   // NPREV == NT
        atomicOr(&bm[tok >> 5], 1u << (tok & 31));
    }
    __syncthreads();

    // warm-up chunk of NT elements: seeds the threshold so steady-state
    // append traffic is tiny.
    {
        int v = tid;
        float x = row[v];
        unsigned w = bm[v >> 5];
        if ((w >> (v & 31)) & 1u) {
            unsigned c16 = (cnt_row[v >> 1] >> ((v & 1) * 16)) & 0xFFFFu;
            x -= 0.5f * (float)c16;
        }
        buf[tid] = ((unsigned long long)ford(x) << 32) | (unsigned)(0xFFFFFFFFu - (unsigned)v);
    }
    __syncthreads();
    if (tid == 0) {
        int ntop = 0;
        for (int i = 0; i < NT; i++) {
            unsigned long long key = buf[i];
            if (ntop < 16) {
                int p = ntop++;
                while (p > 0 && stop[p - 1] < key) { stop[p] = stop[p - 1]; p--; }
                stop[p] = key;
            } else if (key > stop[15]) {
                int p = 15;
                while (p > 0 && stop[p - 1] < key) { stop[p] = stop[p - 1]; p--; }
                stop[p] = key;
            }
        }
        thr_s = stop[15];
        nbuf_s = 0;
    }
    __syncthreads();
    unsigned long long thr = thr_s;

    const int nfull = (Vn - NT) / CH;   // 24 full chunks
    int cb = NT;
    for (int c = 0; c < nfull; c++, cb += CH) {
        float x[8];
#pragma unroll
        for (int j = 0; j < 8; j++) x[j] = row[cb + j * NT + tid];
#pragma unroll
        for (int j = 0; j < 8; j++) {
            int v = cb + j * NT + tid;
            float xv = x[j];
            unsigned w = bm[v >> 5];
            if ((w >> (v & 31)) & 1u) {
                unsigned c16 = (cnt_row[v >> 1] >> ((v & 1) * 16)) & 0xFFFFu;
                xv -= 0.5f * (float)c16;
            }
            unsigned long long key =
                ((unsigned long long)ford(xv) << 32) | (unsigned)(0xFFFFFFFFu - (unsigned)v);
            if (key > thr) { int p = atomicAdd(&nbuf_s, 1); buf[p] = key; }
        }
        __syncthreads();
        if (tid == 0) {
            int n = nbuf_s;
            for (int i = 0; i < n; i++) {
                unsigned long long key = buf[i];
                if (key > stop[15]) {
                    int p = 15;
                    while (p > 0 && stop[p - 1] < key) { stop[p] = stop[p - 1]; p--; }
                    stop[p] = key;
                }
            }
            nbuf_s = 0;
            thr_s = stop[15];
        }
        __syncthreads();
        thr = thr_s;
    }

    // tail (contains v = V-1: EOS penalty applied here only)
    for (int v = cb + tid; v < Vn; v += NT) {
        float xv = row[v];
        if (v == Vn - 1) xv -= 1000.0f;
        unsigned w = bm[v >> 5];
        if ((w >> (v & 31)) & 1u) {
            unsigned c16 = (cnt_row[v >> 1] >> ((v & 1) * 16)) & 0xFFFFu;
            xv -= 0.5f * (float)c16;
        }
        unsigned long long key =
            ((unsigned long long)ford(xv) << 32) | (unsigned)(0xFFFFFFFFu - (unsigned)v);
        if (key > thr) { int p = atomicAdd(&nbuf_s, 1); buf[p] = key; }
    }
    __syncthreads();
    if (tid == 0) {
        int n = nbuf_s;
        for (int i = 0; i < n; i++) {
            unsigned long long key = buf[i];
            if (key > stop[15]) {
                int p = 15;
                while (p > 0 && stop[p - 1] < key) { stop[p] = stop[p - 1]; p--; }
                stop[p] = key;
            }
        }
    }
    __syncthreads();
    if (tid < 16) g_cand[bk * 16 + tid] = stop[tid];
}

// ---------------- global top-16 over KxK candidates + seq outputs ----------------
__global__ __launch_bounds__(NT) void k_select(const float* __restrict__ lp,
                                               const int* __restrict__ beam_seq,
                                               const float* __restrict__ beam_lps,
                                               const float* __restrict__ sums,
                                               const int* __restrict__ d_t,
                                               float* __restrict__ out) {
    __shared__ unsigned long long skey[NT];
    __shared__ int sel_i[16];
    __shared__ float sel_v[16];
    __shared__ int q_s[16], tok_s[16];
    __shared__ float r_s[16];

    const int b = blockIdx.x, tid = threadIdx.x;
    {
        unsigned long long ck = g_cand[b * 256 + tid];
        float aug = finv((unsigned)(ck >> 32));
        float p = sums[b * Kn + (tid >> 4)] + aug;
        // flat index tid = k*K + c  -> matches jax reshape(B, K*K) tie order
        skey[tid] = ((unsigned long long)ford(p) << 32) | (unsigned)(0xFFFFFFFFu - (unsigned)tid);
    }
    __syncthreads();
    if (tid < 32) {
        for (int j = 0; j < 16; j++) {
            unsigned long long best = 0ull;
            for (int m = tid; m < 256; m += 32) {
                unsigned long long kk = skey[m];
                if (kk > best) best = kk;
            }
#pragma unroll
            for (int off = 16; off; off >>= 1) {
                unsigned long long o = __shfl_xor_sync(0xFFFFFFFFu, best, off);
                if (o > best) best = o;
            }
            if (tid == 0) {
                int ii = (int)(0xFFFFFFFFu - (unsigned)(best & 0xFFFFFFFFull));
                sel_i[j] = ii;
                sel_v[j] = finv((unsigned)(best >> 32));
                skey[ii] = 0ull;   // remove winner
            }
            __syncwarp();
        }
    }
    __syncthreads();
    if (tid < 16) {
        int ii = sel_i[tid];
        int q = ii >> 4;
        unsigned long long ck = g_cand[b * 256 + ii];
        int tok = (int)(0xFFFFFFFFu - (unsigned)(ck & 0xFFFFFFFFull));
        float r = lp[(long)(b * Kn + q) * Vn + tok];   // unaugmented, exact
        if (tok == Vn - 1) r -= 1000.0f;
        q_s[tid] = q; tok_s[tid] = tok; r_s[tid] = r;
        g_q[b * Kn + tid] = q;
        out[OFF_SELP + b * Kn + tid] = sel_v[tid];
    }
    __syncthreads();
    const int t = d_t[0];   // low 32 bits: correct for i32 or little-endian i64
    for (int idx = tid; idx < Tn * Kn; idx += NT) {
        int tt = idx >> 4, k = idx & 15;
        float vs, vl;
        if (tt < t) {
            int q = q_s[k];
            vs = (float)beam_seq[(b * Tn + tt) * Kn + q];
            vl = beam_lps[(b * Tn + tt) * Kn + q];
        } else if (tt == t) {
            vs = (float)tok_s[k];
            vl = r_s[k];
        } else {
            vs = (float)beam_seq[(b * Tn + tt) * Kn + k];
            vl = beam_lps[(b * Tn + tt) * Kn + k];
        }
        out[(b * Tn + tt) * Kn + k] = vs;
        out[OFF_LPS + (b * Tn + tt) * Kn + k] = vl;
    }
}

// ---------------- state gather along beam dim (float4) ----------------
__global__ void k_state(const float4* __restrict__ st, float4* __restrict__ dst) {
    int idx = blockIdx.x * blockDim.x + threadIdx.x;   // over S*L*B*K*H/4 = 1048576
    int h4 = idx & (Hn / 4 - 1);
    int rowid = idx >> 7;              // H/4 = 128
    int k = rowid & (Kn - 1);
    int bsl = rowid >> 4;              // (s*L+l)*B + b
    int b = bsl & (Bn - 1);
    int q = __ldg(&g_q[b * Kn + k]);
    dst[idx] = st[((bsl << 4) + q) * (Hn / 4) + h4];
}

extern "C" void kernel_launch(void* const* d_in, const int* in_sizes, int n_in,
                              void* d_out, int out_size) {
    const float* lp   = (const float*)d_in[0];
    const int*   seq  = (const int*)d_in[1];
    const float* lps  = (const float*)d_in[2];
    const float* sums = (const float*)d_in[3];
    const float* st   = (const float*)d_in[4];
    const int*   prev = (const int*)d_in[5];
    const int*   dt   = (const int*)d_in[6];
    float* out = (float*)d_out;

    k_zero_counts<<<Bn, NPREV>>>(prev);
    k_add_counts<<<Bn, NPREV>>>(prev);
    k_beam_topk<<<Bn * Kn, NT>>>(lp, prev);
    k_select<<<Bn, NT>>>(lp, seq, lps, sums, dt, out);
    k_state<<<(2 * 2 * Bn * Kn * (Hn / 4)) / NT, NT>>>((const float4*)st,
                                                       (float4*)(out + OFF_STATE));
}